// round 4
// baseline (speedup 1.0000x reference)
#include <cuda_runtime.h>
#include <math.h>

#define BATCH 32
#define NROI 1000
#define NCLS 81
#define MAXI 100

__device__ __forceinline__ void store_one(int r, float best, int cls,
                                          const float* __restrict__ rois,
                                          const float* __restrict__ bbox,
                                          size_t pb, int b, float4 sd,
                                          float* s_box, float* s_score, short* s_cls)
{
    const float4 dv = *(const float4*)(bbox + (pb + (size_t)r * NCLS + cls) * 4);
    const float4 ro = *(const float4*)(rois + ((size_t)b * NROI + r) * 4);

    float d0 = dv.x * sd.x, d1 = dv.y * sd.y, d2 = dv.z * sd.z, d3 = dv.w * sd.w;
    float h = ro.z - ro.x;
    float w = ro.w - ro.y;
    float cy = ro.x + 0.5f * h + d0 * h;
    float cx = ro.y + 0.5f * w + d1 * w;
    h *= expf(d2);
    w *= expf(d3);
    float ny1 = cy - 0.5f * h;
    float nx1 = cx - 0.5f * w;
    float ny2 = ny1 + h;
    float nx2 = nx1 + w;
    ny1 = fminf(fmaxf(ny1, 0.0f), 1.0f);
    nx1 = fminf(fmaxf(nx1, 0.0f), 1.0f);
    ny2 = fminf(fmaxf(ny2, 0.0f), 1.0f);
    nx2 = fminf(fmaxf(nx2, 0.0f), 1.0f);

    s_box[r * 4 + 0] = ny1;
    s_box[r * 4 + 1] = nx1;
    s_box[r * 4 + 2] = ny2;
    s_box[r * 4 + 3] = nx2;
    s_score[r] = best;
    s_cls[r] = (short)cls;
}

__global__ __launch_bounds__(1024)
void det_fused_kernel(const float* __restrict__ rois,
                      const float* __restrict__ probs,
                      const float* __restrict__ bbox,
                      const float* __restrict__ std_dev,
                      float* __restrict__ out)
{
    __shared__ float s_box[NROI * 4];     // 16 KB
    __shared__ float s_score[NROI];       // 4 KB
    __shared__ short s_cls[NROI];         // 2 KB
    __shared__ short s_cidx[NROI];        // 2 KB (compacted valid orig indices)
    __shared__ short s_ord[NROI];         // 2 KB (sorted rank -> orig index)
    __shared__ unsigned char s_keep[NROI];// 1 KB
    __shared__ float s_out[MAXI * 6];     // 2.4 KB
    __shared__ int s_cnt;

    const int b = blockIdx.x;
    const int t = threadIdx.x;
    const int wid = t >> 5;
    const int lane = t & 31;
    const size_t pb = (size_t)b * NROI * NCLS;

    if (t == 0) s_cnt = 0;
    for (int o = t; o < MAXI * 6; o += 1024) s_out[o] = 0.0f;

    const float4 sd = *(const float4*)std_dev;

    // ---------- Phase 1: warp-per-ROI coalesced argmax + box regression ----------
    // warp w handles ROIs w, w+32, ... ; 2 ROIs per iteration for ILP
    for (int it = 0; it < 32; it += 2) {
        const int r0 = wid + it * 32;          // always < 1000 (max 991)
        const int r1 = r0 + 32;
        const bool a1 = (r1 < NROI);

        const float* p0 = probs + pb + (size_t)r0 * NCLS;
        float b0, b1v; int i0, i1;
        {
            float v0 = p0[lane];
            float v1 = p0[lane + 32];
            float v2 = (lane < NCLS - 64) ? p0[lane + 64] : -INFINITY;
            b0 = v0; i0 = lane;
            if (v1 > b0) { b0 = v1; i0 = lane + 32; }
            if (v2 > b0) { b0 = v2; i0 = lane + 64; }
        }
        if (a1) {
            const float* p1 = probs + pb + (size_t)r1 * NCLS;
            float v0 = p1[lane];
            float v1 = p1[lane + 32];
            float v2 = (lane < NCLS - 64) ? p1[lane + 64] : -INFINITY;
            b1v = v0; i1 = lane;
            if (v1 > b1v) { b1v = v1; i1 = lane + 32; }
            if (v2 > b1v) { b1v = v2; i1 = lane + 64; }
        } else { b1v = -INFINITY; i1 = 0; }

        #pragma unroll
        for (int off = 16; off > 0; off >>= 1) {
            float ov0 = __shfl_down_sync(0xffffffffu, b0,  off);
            int   oi0 = __shfl_down_sync(0xffffffffu, i0,  off);
            float ov1 = __shfl_down_sync(0xffffffffu, b1v, off);
            int   oi1 = __shfl_down_sync(0xffffffffu, i1,  off);
            if (ov0 > b0  || (ov0 == b0  && oi0 < i0)) { b0  = ov0; i0 = oi0; }
            if (ov1 > b1v || (ov1 == b1v && oi1 < i1)) { b1v = ov1; i1 = oi1; }
        }

        if (lane == 0) {
            store_one(r0, b0, i0, rois, bbox, pb, b, sd, s_box, s_score, s_cls);
            if (a1) store_one(r1, b1v, i1, rois, bbox, pb, b, sd, s_box, s_score, s_cls);
        }
    }
    __syncthreads();

    // ---------- Phase 2: compact valid entries ----------
    if (t < NROI) {
        if (s_cls[t] > 0 && s_score[t] >= 0.7f) {
            int pos = atomicAdd(&s_cnt, 1);
            s_cidx[pos] = (short)t;
        }
    }
    __syncthreads();
    const int M = s_cnt;

    // ---------- Phase 3: rank sort (score desc, orig index asc) ----------
    if (t < M) {
        const short ki = s_cidx[t];
        const float ks = s_score[ki];
        int rank = 0;
        for (int j = 0; j < M; ++j) {
            short kj = s_cidx[j];
            float js = s_score[kj];
            rank += (js > ks) || (js == ks && kj < ki);
        }
        s_ord[rank] = ki;
        s_keep[rank] = 1;
    }
    __syncthreads();

    // ---------- Phase 4: greedy class-aware NMS (warp 0, lanes parallelize j) ----------
    if (wid == 0) {
        for (int i = 0; i < M; ++i) {
            if (!s_keep[i]) continue;          // uniform across warp
            const int oi = s_ord[i];
            const float iy1 = s_box[oi * 4 + 0];
            const float ix1 = s_box[oi * 4 + 1];
            const float iy2 = s_box[oi * 4 + 2];
            const float ix2 = s_box[oi * 4 + 3];
            const short ic  = s_cls[oi];
            const float ai  = (iy2 - iy1) * (ix2 - ix1);
            for (int j = i + 1 + lane; j < M; j += 32) {
                if (!s_keep[j]) continue;
                const int oj = s_ord[j];
                if (s_cls[oj] != ic) continue;
                float jy1 = s_box[oj * 4 + 0];
                float jx1 = s_box[oj * 4 + 1];
                float jy2 = s_box[oj * 4 + 2];
                float jx2 = s_box[oj * 4 + 3];
                float aj = (jy2 - jy1) * (jx2 - jx1);
                float ih = fmaxf(fminf(iy2, jy2) - fmaxf(iy1, jy1), 0.0f);
                float iw = fmaxf(fminf(ix2, jx2) - fmaxf(ix1, jx1), 0.0f);
                float inter = ih * iw;
                float iou = inter / fmaxf(ai + aj - inter, 1e-8f);
                if (iou > 0.3f) s_keep[j] = 0;   // each lane writes distinct j
            }
            __syncwarp();
        }
    }
    __syncthreads();

    // ---------- Phase 5: slot assignment + staged output ----------
    if (t < M && s_keep[t]) {
        int slot = 0;
        for (int j = 0; j < t; ++j) slot += s_keep[j];
        if (slot < MAXI) {
            const int o = s_ord[t];
            s_out[slot * 6 + 0] = s_box[o * 4 + 0];
            s_out[slot * 6 + 1] = s_box[o * 4 + 1];
            s_out[slot * 6 + 2] = s_box[o * 4 + 2];
            s_out[slot * 6 + 3] = s_box[o * 4 + 3];
            s_out[slot * 6 + 4] = (float)s_cls[o];
            s_out[slot * 6 + 5] = s_score[o];
        }
    }
    __syncthreads();

    float* ob = out + (size_t)b * MAXI * 6;
    for (int o = t; o < MAXI * 6; o += 1024) ob[o] = s_out[o];
}

extern "C" void kernel_launch(void* const* d_in, const int* in_sizes, int n_in,
                              void* d_out, int out_size)
{
    const float* rois    = (const float*)d_in[0];
    const float* probs   = (const float*)d_in[1];
    const float* bbox    = (const float*)d_in[2];
    const float* std_dev = (const float*)d_in[3];
    float* out = (float*)d_out;
    det_fused_kernel<<<BATCH, 1024>>>(rois, probs, bbox, std_dev, out);
}

// round 5
// speedup vs baseline: 1.8564x; 1.8564x over previous
#include <cuda_runtime.h>
#include <math.h>

#define BATCH 32
#define NROI 1000
#define NCLS 81
#define MAXI 100
#define NTOT (BATCH * NROI)
#define RPW 4

// compacted per-image lists (device globals: zero-init, reset by detB each run)
__device__ float4 g_cbox[NTOT];
__device__ float4 g_cmeta[NTOT];   // {score, cls, origidx, 0}
__device__ int    g_cnt[BATCH];

// ---------------------------------------------------------------------------
// Kernel A: full-chip argmax; box regression + compaction ONLY for valid ROIs
// ---------------------------------------------------------------------------
__global__ __launch_bounds__(256)
void detA_kernel(const float* __restrict__ rois,
                 const float* __restrict__ probs,
                 const float* __restrict__ bbox,
                 const float* __restrict__ std_dev)
{
    const int warp = (blockIdx.x * 256 + threadIdx.x) >> 5;
    const int lane = threadIdx.x & 31;
    const int r0 = warp * RPW;
    if (r0 >= NTOT) return;

    float best[RPW];
    int   bi[RPW];

    #pragma unroll
    for (int k = 0; k < RPW; ++k) {
        const float* p = probs + (size_t)(r0 + k) * NCLS;
        float v0 = p[lane];
        float v1 = p[lane + 32];
        float v2 = (lane < NCLS - 64) ? p[lane + 64] : -INFINITY;
        best[k] = v0; bi[k] = lane;
        if (v1 > best[k]) { best[k] = v1; bi[k] = lane + 32; }
        if (v2 > best[k]) { best[k] = v2; bi[k] = lane + 64; }
    }

    #pragma unroll
    for (int off = 16; off > 0; off >>= 1) {
        #pragma unroll
        for (int k = 0; k < RPW; ++k) {
            float ov = __shfl_down_sync(0xffffffffu, best[k], off);
            int   oi = __shfl_down_sync(0xffffffffu, bi[k],   off);
            if (ov > best[k] || (ov == best[k] && oi < bi[k])) { best[k] = ov; bi[k] = oi; }
        }
    }

    if (lane == 0) {
        const float4 sd = *(const float4*)std_dev;
        #pragma unroll
        for (int k = 0; k < RPW; ++k) {
            if (bi[k] <= 0 || best[k] < 0.7f) continue;   // skip heavy work for invalid
            const int ri  = r0 + k;
            const int img = ri / NROI;
            const int roi = ri - img * NROI;

            const float4 dv = *(const float4*)(bbox + ((size_t)ri * NCLS + bi[k]) * 4);
            const float4 r  = *(const float4*)(rois + (size_t)ri * 4);

            float d0 = dv.x * sd.x, d1 = dv.y * sd.y, d2 = dv.z * sd.z, d3 = dv.w * sd.w;
            float h = r.z - r.x;
            float w = r.w - r.y;
            float cy = r.x + 0.5f * h + d0 * h;
            float cx = r.y + 0.5f * w + d1 * w;
            h *= expf(d2);
            w *= expf(d3);
            float ny1 = cy - 0.5f * h;
            float nx1 = cx - 0.5f * w;
            float ny2 = ny1 + h;
            float nx2 = nx1 + w;
            ny1 = fminf(fmaxf(ny1, 0.0f), 1.0f);
            nx1 = fminf(fmaxf(nx1, 0.0f), 1.0f);
            ny2 = fminf(fmaxf(ny2, 0.0f), 1.0f);
            nx2 = fminf(fmaxf(nx2, 0.0f), 1.0f);

            int pos = atomicAdd(&g_cnt[img], 1);
            g_cbox[img * NROI + pos]  = make_float4(ny1, nx1, ny2, nx2);
            g_cmeta[img * NROI + pos] = make_float4(best[k], (float)bi[k], (float)roi, 0.0f);
        }
    }
}

// ---------------------------------------------------------------------------
// Kernel B: tiny — sort M compacted entries, greedy NMS, emit; reset counters
// ---------------------------------------------------------------------------
#define BT 256
__global__ __launch_bounds__(BT)
void detB_kernel(float* __restrict__ out)
{
    __shared__ float s_score[NROI];
    __shared__ short s_cls[NROI];
    __shared__ short s_idx[NROI];
    __shared__ float s_sbox[NROI * 4];    // sorted boxes
    __shared__ float s_sscore[NROI];
    __shared__ short s_scls[NROI];
    __shared__ unsigned char s_keep[NROI];
    __shared__ float s_out[MAXI * 6];

    const int b = blockIdx.x;
    const int t = threadIdx.x;
    const int wid = t >> 5;
    const int lane = t & 31;
    const int base = b * NROI;

    const int M = min(g_cnt[b], NROI);

    for (int o = t; o < MAXI * 6; o += BT) s_out[o] = 0.0f;

    for (int e = t; e < M; e += BT) {
        float4 m = g_cmeta[base + e];
        s_score[e] = m.x;
        s_cls[e]   = (short)m.y;
        s_idx[e]   = (short)m.z;
    }
    __syncthreads();

    // rank sort: (score desc, orig index asc) — makes atomic order irrelevant
    for (int e = t; e < M; e += BT) {
        const float ks = s_score[e];
        const short ki = s_idx[e];
        int rank = 0;
        for (int j = 0; j < M; ++j) {
            float js = s_score[j];
            rank += (js > ks) || (js == ks && s_idx[j] < ki);
        }
        float4 bx = g_cbox[base + e];
        s_sbox[rank * 4 + 0] = bx.x;
        s_sbox[rank * 4 + 1] = bx.y;
        s_sbox[rank * 4 + 2] = bx.z;
        s_sbox[rank * 4 + 3] = bx.w;
        s_sscore[rank] = ks;
        s_scls[rank]   = s_cls[e];
        s_keep[rank]   = 1;
    }
    __syncthreads();

    // greedy class-aware NMS: warp 0, lanes parallelize the j sweep
    if (wid == 0) {
        for (int i = 0; i < M; ++i) {
            if (!s_keep[i]) continue;
            const float iy1 = s_sbox[i * 4 + 0];
            const float ix1 = s_sbox[i * 4 + 1];
            const float iy2 = s_sbox[i * 4 + 2];
            const float ix2 = s_sbox[i * 4 + 3];
            const short ic  = s_scls[i];
            const float ai  = (iy2 - iy1) * (ix2 - ix1);
            for (int j = i + 1 + lane; j < M; j += 32) {
                if (!s_keep[j] || s_scls[j] != ic) continue;
                float jy1 = s_sbox[j * 4 + 0];
                float jx1 = s_sbox[j * 4 + 1];
                float jy2 = s_sbox[j * 4 + 2];
                float jx2 = s_sbox[j * 4 + 3];
                float aj = (jy2 - jy1) * (jx2 - jx1);
                float ih = fmaxf(fminf(iy2, jy2) - fmaxf(iy1, jy1), 0.0f);
                float iw = fmaxf(fminf(ix2, jx2) - fmaxf(ix1, jx1), 0.0f);
                float inter = ih * iw;
                float iou = inter / fmaxf(ai + aj - inter, 1e-8f);
                if (iou > 0.3f) s_keep[j] = 0;
            }
            __syncwarp();
        }
    }
    __syncthreads();

    // slot assignment + staged output
    for (int e = t; e < M; e += BT) {
        if (!s_keep[e]) continue;
        int slot = 0;
        for (int j = 0; j < e; ++j) slot += s_keep[j];
        if (slot < MAXI) {
            s_out[slot * 6 + 0] = s_sbox[e * 4 + 0];
            s_out[slot * 6 + 1] = s_sbox[e * 4 + 1];
            s_out[slot * 6 + 2] = s_sbox[e * 4 + 2];
            s_out[slot * 6 + 3] = s_sbox[e * 4 + 3];
            s_out[slot * 6 + 4] = (float)s_scls[e];
            s_out[slot * 6 + 5] = s_sscore[e];
        }
    }
    __syncthreads();

    float* ob = out + (size_t)b * MAXI * 6;
    for (int o = t; o < MAXI * 6; o += BT) ob[o] = s_out[o];

    if (t == 0) g_cnt[b] = 0;   // reset for next graph replay (zero-init initially)
}

extern "C" void kernel_launch(void* const* d_in, const int* in_sizes, int n_in,
                              void* d_out, int out_size)
{
    const float* rois    = (const float*)d_in[0];
    const float* probs   = (const float*)d_in[1];
    const float* bbox    = (const float*)d_in[2];
    const float* std_dev = (const float*)d_in[3];
    float* out = (float*)d_out;

    const int warpsA  = NTOT / RPW;                 // 8000
    const int blocksA = (warpsA * 32 + 255) / 256;  // 1000
    detA_kernel<<<blocksA, 256>>>(rois, probs, bbox, std_dev);
    detB_kernel<<<BATCH, BT>>>(out);
}